// round 8
// baseline (speedup 1.0000x reference)
#include <cuda_runtime.h>

#define CHANNELS  8
#define IN_CH     8
#define NPARAMS   169      // 80 + 64 + 8 + 8 + 8 + 1
#define H_        128
#define W_        192
#define HW_       (H_ * W_)
#define GI        4        // instances per block
#define TILE_R    8        // logit rows per block (output rows 2*TILE_R)
#define NROWS     (TILE_R + 1)   // + 1 halo row above

typedef unsigned long long u64;

// ---- packed fp32x2 helpers (Blackwell) -------------------------------------
__device__ __forceinline__ u64 fma2(u64 a, u64 b, u64 c) {
    u64 d;
    asm("fma.rn.f32x2 %0, %1, %2, %3;" : "=l"(d) : "l"(a), "l"(b), "l"(c));
    return d;
}
__device__ __forceinline__ u64 pack2(float lo, float hi) {
    u64 d;
    asm("mov.b64 %0, {%1, %2};" : "=l"(d) : "f"(lo), "f"(hi));
    return d;
}
__device__ __forceinline__ void unpack2(u64 v, float& lo, float& hi) {
    asm("mov.b64 {%0, %1}, %2;" : "=f"(lo), "=f"(hi) : "l"(v));
}
__device__ __forceinline__ u64 relu2(u64 v) {
    float lo, hi;
    unpack2(v, lo, hi);
    return pack2(fmaxf(lo, 0.0f), fmaxf(hi, 0.0f));
}

// ---------------------------------------------------------------------------
// Fused kernel: one block = 4 instances x 8-row logit tile.
// Phase 1 (round-2 proven MLP body, 4 px/thread-unit): compute 9 logit rows
//   (1 clamped halo row) for each of the 4 instances into shared memory.
// Phase 2: aligned 2x bilinear upsample from shared straight to gmem:
//   O[2r,  2c  ] = 0.25*(L[r-1,c-1] + L[r-1,c] + L[r,c-1] + L[r,c])
//   O[2r,  2c+1] = 0.5 *(L[r-1,c]   + L[r,c])
//   O[2r+1,2c  ] = 0.5 *(L[r,c-1]   + L[r,c])
//   O[2r+1,2c+1] =       L[r,c]          (r-1, c-1 clamped at 0)
// This deletes the 12.6MB logit write + 25MB logit read of the split design.
// ---------------------------------------------------------------------------
__global__ __launch_bounds__(128, 4)
void fused_mask_kernel(const float* __restrict__ mask_feats,   // (N, 8, H, W)
                       const float* __restrict__ params,       // (n_inst, 169)
                       const float* __restrict__ inst_loc,     // (n_inst, 2)
                       const float* __restrict__ soi_tab,      // (6,)
                       const int*   __restrict__ im_inds,      // (n_inst,)
                       const int*   __restrict__ fpn_levels,   // (n_inst,)
                       float*       __restrict__ out,
                       int n_inst)
{
    __shared__ __align__(16) float2 sp2[GI * NPARAMS];          // 5408 B
    __shared__ __align__(16) float  st[GI][NROWS * W_];         // 27648 B
    __shared__ float s_ix[GI], s_iy[GI], s_isoi[GI];
    __shared__ int   s_im[GI];

    const int r0  = blockIdx.x * TILE_R;        // first output logit row
    const int n0  = blockIdx.y * GI;            // first instance
    const int tid = threadIdx.x;

    const int g_cnt = min(GI, n_inst - n0);
    for (int i = tid; i < g_cnt * NPARAMS; i += 128) {
        float v = params[(size_t)n0 * NPARAMS + i];
        sp2[i] = make_float2(v, v);
    }
    if (tid < GI && n0 + tid < n_inst) {
        int n = n0 + tid;
        s_ix[tid]   = inst_loc[2 * n + 0];
        s_iy[tid]   = inst_loc[2 * n + 1];
        s_isoi[tid] = 1.0f / soi_tab[fpn_levels[n]];
        s_im[tid]   = im_inds[n];
    }
    __syncthreads();

    // ---------------- Phase 1: MLP into shared tiles ------------------------
    #pragma unroll 1
    for (int g = 0; g < g_cnt; g++) {
        const u64* prm = reinterpret_cast<const u64*>(sp2) + g * NPARAMS;
        const float s  = s_isoi[g];
        const float ix = s_ix[g], iy = s_iy[g];
        const float* featbase = mask_feats + (size_t)s_im[g] * IN_CH * HW_;

        // units: 9 rows x 48 strips of 4 px = 432
        #pragma unroll 1
        for (int u = tid; u < NROWS * (W_ / 4); u += 128) {
            const int row = u / (W_ / 4);
            const int c0  = (u % (W_ / 4)) * 4;
            const int gr  = max(r0 + row - 1, 0);   // global logit row (halo clamp)

            const float dx  = ix - ((float)c0 * 8.0f + 4.0f);
            const float ryv = (iy - ((float)gr * 8.0f + 4.0f)) * s;
            const u64 rx01 = pack2(dx * s,           (dx - 8.0f)  * s);
            const u64 rx23 = pack2((dx - 16.0f) * s, (dx - 24.0f) * s);
            const u64 ry   = pack2(ryv, ryv);

            const float4* f4 = reinterpret_cast<const float4*>(
                featbase + (size_t)gr * W_ + c0);
            u64 fp01[IN_CH], fp23[IN_CH];
            #pragma unroll
            for (int c = 0; c < IN_CH; c++) {
                float4 v = f4[c * (HW_ / 4)];
                fp01[c] = pack2(v.x, v.y);
                fp23[c] = pack2(v.z, v.w);
            }

            // layer 0: 8 x 10, ReLU
            u64 h01[CHANNELS], h23[CHANNELS];
            #pragma unroll
            for (int o = 0; o < CHANNELS; o++) {
                u64 b  = prm[152 + o];
                u64 a0 = b, a1 = b;
                u64 wx = prm[o * 10 + 0];
                u64 wy = prm[o * 10 + 1];
                a0 = fma2(wx, rx01, a0);  a1 = fma2(wx, rx23, a1);
                a0 = fma2(wy, ry,   a0);  a1 = fma2(wy, ry,   a1);
                #pragma unroll
                for (int c = 0; c < IN_CH; c++) {
                    u64 w = prm[o * 10 + 2 + c];
                    a0 = fma2(w, fp01[c], a0);
                    a1 = fma2(w, fp23[c], a1);
                }
                h01[o] = relu2(a0);
                h23[o] = relu2(a1);
            }

            // layer 1 (ReLU) with layer 2 fused
            u64 acc0 = prm[168], acc1 = prm[168];
            #pragma unroll
            for (int o = 0; o < CHANNELS; o++) {
                u64 b1 = prm[160 + o];
                u64 a0 = b1, a1 = b1;
                #pragma unroll
                for (int c = 0; c < CHANNELS; c++) {
                    u64 w = prm[80 + o * 8 + c];
                    a0 = fma2(w, h01[c], a0);
                    a1 = fma2(w, h23[c], a1);
                }
                u64 w2 = prm[144 + o];
                acc0 = fma2(w2, relu2(a0), acc0);
                acc1 = fma2(w2, relu2(a1), acc1);
            }

            float o0, o1, o2, o3;
            unpack2(acc0, o0, o1);
            unpack2(acc1, o2, o3);
            *reinterpret_cast<float4*>(&st[g][row * W_ + c0]) =
                make_float4(o0, o1, o2, o3);
        }
    }

    __syncthreads();

    // ---------------- Phase 2: upsample from shared tiles -------------------
    // units: GI x 8 rows x 48 strips of 4 input px = 1536 (12 per thread)
    #pragma unroll 1
    for (int u = tid; u < g_cnt * TILE_R * (W_ / 4); u += 128) {
        const int c0 = (u % (W_ / 4)) * 4;
        const int ru = u / (W_ / 4);            // 0..31
        const int lr = ru % TILE_R;             // local logit row within tile
        const int g  = ru / TILE_R;

        const float* top = &st[g][lr * W_];        // L[r-1] (halo-shifted)
        const float* bot = &st[g][(lr + 1) * W_];  // L[r]
        const int cm = max(c0 - 1, 0);

        const float4 A  = *reinterpret_cast<const float4*>(top + c0);
        const float4 B  = *reinterpret_cast<const float4*>(bot + c0);
        const float  aL = top[cm];
        const float  bL = bot[cm];

        const float sL = aL + bL;
        const float s0 = A.x + B.x;
        const float s1 = A.y + B.y;
        const float s2 = A.z + B.z;
        const float s3 = A.w + B.w;

        float4 r0a, r0b, r1a, r1b;
        r0a.x = 0.25f * (sL + s0);  r0a.y = 0.5f * s0;
        r0a.z = 0.25f * (s0 + s1);  r0a.w = 0.5f * s1;
        r0b.x = 0.25f * (s1 + s2);  r0b.y = 0.5f * s2;
        r0b.z = 0.25f * (s2 + s3);  r0b.w = 0.5f * s3;

        r1a.x = 0.5f * (bL + B.x);  r1a.y = B.x;
        r1a.z = 0.5f * (B.x + B.y); r1a.w = B.y;
        r1b.x = 0.5f * (B.y + B.z); r1b.y = B.z;
        r1b.z = 0.5f * (B.z + B.w); r1b.w = B.w;

        const int r = r0 + lr;                  // global logit row
        float* o = out + (size_t)(n0 + g) * (4 * HW_)
                       + (size_t)(2 * r) * (2 * W_) + 2 * c0;
        reinterpret_cast<float4*>(o)[0]          = r0a;
        reinterpret_cast<float4*>(o)[1]          = r0b;
        reinterpret_cast<float4*>(o + 2 * W_)[0] = r1a;
        reinterpret_cast<float4*>(o + 2 * W_)[1] = r1b;
    }
}

// ---------------------------------------------------------------------------
extern "C" void kernel_launch(void* const* d_in, const int* in_sizes, int n_in,
                              void* d_out, int out_size)
{
    const float* mask_feats = (const float*)d_in[0];
    const float* params     = (const float*)d_in[1];
    const float* inst_loc   = (const float*)d_in[2];
    const float* soi_tab    = (const float*)d_in[3];
    const int*   im_inds    = (const int*)d_in[4];
    const int*   fpn_levels = (const int*)d_in[5];
    float*       out        = (float*)d_out;

    const int n_inst = in_sizes[1] / NPARAMS;   // 128

    dim3 grid(H_ / TILE_R, (n_inst + GI - 1) / GI);   // 16 x 32 = 512 blocks
    fused_mask_kernel<<<grid, 128>>>(mask_feats, params, inst_loc, soi_tab,
                                     im_inds, fpn_levels, out, n_inst);
}

// round 9
// speedup vs baseline: 5.6190x; 5.6190x over previous
#include <cuda_runtime.h>

#define CHANNELS  8
#define IN_CH     8
#define NPARAMS   169      // 80 + 64 + 8 + 8 + 8 + 1
#define H_        128
#define W_        192
#define HW_       (H_ * W_)
#define GI        4        // instances per block in the head kernel
#define MAX_INST  128

// Logits scratch: 128 * 24576 * 4B = 12.6 MB (L2-resident on GB300)
__device__ float g_logits[MAX_INST * HW_];

typedef unsigned long long u64;

// ---- packed fp32x2 helpers (Blackwell) -------------------------------------
__device__ __forceinline__ u64 fma2(u64 a, u64 b, u64 c) {
    u64 d;
    asm("fma.rn.f32x2 %0, %1, %2, %3;" : "=l"(d) : "l"(a), "l"(b), "l"(c));
    return d;
}
__device__ __forceinline__ u64 pack2(float lo, float hi) {
    u64 d;
    asm("mov.b64 %0, {%1, %2};" : "=l"(d) : "f"(lo), "f"(hi));
    return d;
}
__device__ __forceinline__ void unpack2(u64 v, float& lo, float& hi) {
    asm("mov.b64 {%0, %1}, %2;" : "=f"(lo), "=f"(hi) : "l"(v));
}
__device__ __forceinline__ u64 relu2(u64 v) {
    float lo, hi;
    unpack2(v, lo, hi);
    return pack2(fmaxf(lo, 0.0f), fmaxf(hi, 0.0f));
}

// ---------------------------------------------------------------------------
// Kernel 1: dynamic mask head MLP (round-2 exact form — measured at the fp32
// FFMA roofline, 36.4 TF/s). One thread = 4 consecutive pixels (2x f32x2),
// GI instances per block; weights broadcast from shared as duplicated float2.
// ---------------------------------------------------------------------------
__global__ __launch_bounds__(256)
void mask_head_kernel(const float* __restrict__ mask_feats,   // (N, 8, H, W)
                      const float* __restrict__ params,       // (n_inst, 169)
                      const float* __restrict__ inst_loc,     // (n_inst, 2)
                      const float* __restrict__ soi_tab,      // (6,)
                      const int*   __restrict__ im_inds,      // (n_inst,)
                      const int*   __restrict__ fpn_levels,   // (n_inst,)
                      int n_inst)
{
    __shared__ float2 sp2[GI * NPARAMS];
    __shared__ float  s_ix[GI], s_iy[GI], s_isoi[GI];
    __shared__ int    s_im[GI];

    const int n0  = blockIdx.y * GI;
    const int tid = threadIdx.x;

    const int g_cnt = min(GI, n_inst - n0);
    for (int i = tid; i < g_cnt * NPARAMS; i += 256) {
        float v = params[(size_t)n0 * NPARAMS + i];
        sp2[i] = make_float2(v, v);
    }
    if (tid < GI && n0 + tid < n_inst) {
        int n = n0 + tid;
        s_ix[tid]   = inst_loc[2 * n + 0];
        s_iy[tid]   = inst_loc[2 * n + 1];
        s_isoi[tid] = 1.0f / soi_tab[fpn_levels[n]];
        s_im[tid]   = im_inds[n];
    }
    __syncthreads();

    const int p0 = (blockIdx.x * 256 + tid) * 4;   // 4 consecutive px, same row
    const int px = p0 % W_;
    const int py = p0 / W_;
    const float lx0 = (float)px * 8.0f + 4.0f;     // MASK_FEAT_STRIDE = 8
    const float ly  = (float)py * 8.0f + 4.0f;

    #pragma unroll 1
    for (int g = 0; g < g_cnt; g++) {
        const u64* prm = reinterpret_cast<const u64*>(sp2) + g * NPARAMS;

        const float s  = s_isoi[g];
        const float dx = s_ix[g] - lx0;
        const float ryv = (s_iy[g] - ly) * s;
        const u64 rx01 = pack2(dx * s,           (dx - 8.0f)  * s);
        const u64 rx23 = pack2((dx - 16.0f) * s, (dx - 24.0f) * s);
        const u64 ry   = pack2(ryv, ryv);

        const float4* f4 = reinterpret_cast<const float4*>(
            mask_feats + (size_t)s_im[g] * IN_CH * HW_ + p0);
        u64 fp01[IN_CH], fp23[IN_CH];
        #pragma unroll
        for (int c = 0; c < IN_CH; c++) {
            float4 v = f4[c * (HW_ / 4)];
            fp01[c] = pack2(v.x, v.y);
            fp23[c] = pack2(v.z, v.w);
        }

        // layer 0: 8 x 10, ReLU
        u64 h01[CHANNELS], h23[CHANNELS];
        #pragma unroll
        for (int o = 0; o < CHANNELS; o++) {
            u64 b  = prm[152 + o];
            u64 a0 = b, a1 = b;
            u64 wx = prm[o * 10 + 0];
            u64 wy = prm[o * 10 + 1];
            a0 = fma2(wx, rx01, a0);  a1 = fma2(wx, rx23, a1);
            a0 = fma2(wy, ry,   a0);  a1 = fma2(wy, ry,   a1);
            #pragma unroll
            for (int c = 0; c < IN_CH; c++) {
                u64 w = prm[o * 10 + 2 + c];
                a0 = fma2(w, fp01[c], a0);
                a1 = fma2(w, fp23[c], a1);
            }
            h01[o] = relu2(a0);
            h23[o] = relu2(a1);
        }

        // layer 1 (ReLU) with layer 2 fused
        u64 acc0 = prm[168], acc1 = prm[168];
        #pragma unroll
        for (int o = 0; o < CHANNELS; o++) {
            u64 b1 = prm[160 + o];
            u64 a0 = b1, a1 = b1;
            #pragma unroll
            for (int c = 0; c < CHANNELS; c++) {
                u64 w = prm[80 + o * 8 + c];
                a0 = fma2(w, h01[c], a0);
                a1 = fma2(w, h23[c], a1);
            }
            u64 w2 = prm[144 + o];
            acc0 = fma2(w2, relu2(a0), acc0);
            acc1 = fma2(w2, relu2(a1), acc1);
        }

        float o0, o1, o2, o3;
        unpack2(acc0, o0, o1);
        unpack2(acc1, o2, o3);
        *reinterpret_cast<float4*>(g_logits + (size_t)(n0 + g) * HW_ + p0) =
            make_float4(o0, o1, o2, o3);
    }
}

// ---------------------------------------------------------------------------
// Kernel 2: aligned 2x bilinear upsample — proven 2 px/thread shape with a
// ZERO div/mod mapping: block (96,2), grid (H/2, n_inst).
//   c0 = 2*threadIdx.x, r = blockIdx.x*2 + threadIdx.y, n = blockIdx.y.
//   O[2r,  2c  ] = 0.25*(L[r-1,c-1] + L[r-1,c] + L[r,c-1] + L[r,c])
//   O[2r,  2c+1] = 0.5 *(L[r-1,c]   + L[r,c])
//   O[2r+1,2c  ] = 0.5 *(L[r,c-1]   + L[r,c])
//   O[2r+1,2c+1] =       L[r,c]          (r-1, c-1 clamped at 0)
// ---------------------------------------------------------------------------
__global__ __launch_bounds__(192)
void upsample_kernel(float* __restrict__ out)
{
    const int c0 = threadIdx.x * 2;                  // 0..190
    const int r  = blockIdx.x * 2 + threadIdx.y;     // logit row
    const int n  = blockIdx.y;                       // instance

    const float* Ln = g_logits + (size_t)n * HW_;
    const int rm = max(r - 1, 0);
    const int cm = max(c0 - 1, 0);

    // ---- all 4 loads issued before any compute ----
    const float2 t01 = *reinterpret_cast<const float2*>(Ln + rm * W_ + c0);
    const float2 u01 = *reinterpret_cast<const float2*>(Ln + r  * W_ + c0);
    const float  tm  = Ln[rm * W_ + cm];
    const float  um  = Ln[r  * W_ + cm];

    float4 r0, r1;
    r0.x = 0.25f * ((tm + t01.x) + (um + u01.x));
    r0.y = 0.5f  * (t01.x + u01.x);
    r0.z = 0.25f * ((t01.x + t01.y) + (u01.x + u01.y));
    r0.w = 0.5f  * (t01.y + u01.y);
    r1.x = 0.5f  * (um + u01.x);
    r1.y = u01.x;
    r1.z = 0.5f  * (u01.x + u01.y);
    r1.w = u01.y;

    float* o = out + (size_t)n * (4 * HW_) + (size_t)(2 * r) * (2 * W_) + 2 * c0;
    *reinterpret_cast<float4*>(o)          = r0;
    *reinterpret_cast<float4*>(o + 2 * W_) = r1;
}

// ---------------------------------------------------------------------------
extern "C" void kernel_launch(void* const* d_in, const int* in_sizes, int n_in,
                              void* d_out, int out_size)
{
    const float* mask_feats = (const float*)d_in[0];
    const float* params     = (const float*)d_in[1];
    const float* inst_loc   = (const float*)d_in[2];
    const float* soi_tab    = (const float*)d_in[3];
    const int*   im_inds    = (const int*)d_in[4];
    const int*   fpn_levels = (const int*)d_in[5];
    float*       out        = (float*)d_out;

    const int n_inst = in_sizes[1] / NPARAMS;   // 128

    dim3 grid1(HW_ / (256 * 4), (n_inst + GI - 1) / GI);   // 24 x 32
    mask_head_kernel<<<grid1, 256>>>(mask_feats, params, inst_loc, soi_tab,
                                     im_inds, fpn_levels, n_inst);

    dim3 grid2(H_ / 2, n_inst);                            // 64 x 128
    dim3 blk2(96, 2);                                      // 192 threads
    upsample_kernel<<<grid2, blk2>>>(out);
}